// round 3
// baseline (speedup 1.0000x reference)
#include <cuda_runtime.h>
#include <cstdint>
#include <math.h>

// ---------------------------------------------------------------------------
// ImprovedGraphLSTMCell  (N=8192, K=8, H=512, X=512)
// tf32 mma.sync m16n8k8, fp32 accumulate, rna-rounded operands.
// R3: 256x128 block / 64x64 warp tiles, cp.async 3-stage pipeline,
//     XOR-swizzled conflict-free smem, pre-converted tf32 weights/x.
// ---------------------------------------------------------------------------

namespace {
constexpr int Nn  = 8192;
constexpr int Kmb = 8;
constexpr int Hh  = 512;
constexpr int Xx  = 512;
constexpr int NK  = Nn * Kmb;     // 65536
constexpr int H2v = 2 * Hh;       // 1024
constexpr int H3v = 3 * Hh;       // 1536

constexpr int BM = 256, BN = 128, BK = 32;
constexpr int NSTAGE = 3;
constexpr int A_ELEM = BM * BK;           // 8192 floats
constexpr int B_ELEM = BK * BN;           // 4096 floats
constexpr int STAGE_ELEM = A_ELEM + B_ELEM;
constexpr int SMEM_BYTES = NSTAGE * STAGE_ELEM * 4;  // 147456
}

// Scratch (device globals — no allocation allowed)
__device__ float g_wfx[Nn * Hh];
__device__ float g_iou[Nn * H3v];
__device__ float g_hsum2[Nn * H2v];
__device__ float g_cagg[Nn * Hh];
__device__ float g_xt[Nn * Xx];
__device__ float g_wiou_t[Xx * H3v];
__device__ float g_wf_t[Xx * Hh];
__device__ float g_uiou_t[H2v * H3v];
__device__ float g_uf_t[H2v * Hh];

__device__ __forceinline__ uint32_t tf32b(float x) {
    uint32_t r;
    asm("cvt.rna.tf32.f32 %0, %1;" : "=r"(r) : "f"(x));
    return r;
}
__device__ __forceinline__ float to_tf32(float x) { return __uint_as_float(tf32b(x)); }

__device__ __forceinline__ void mma8(float c[4],
                                     uint32_t a0, uint32_t a1, uint32_t a2, uint32_t a3,
                                     uint32_t b0, uint32_t b1) {
    asm volatile(
        "mma.sync.aligned.m16n8k8.row.col.f32.tf32.tf32.f32 "
        "{%0,%1,%2,%3}, {%4,%5,%6,%7}, {%8,%9}, {%0,%1,%2,%3};\n"
        : "+f"(c[0]), "+f"(c[1]), "+f"(c[2]), "+f"(c[3])
        : "r"(a0), "r"(a1), "r"(a2), "r"(a3), "r"(b0), "r"(b1));
}

__device__ __forceinline__ void cp16(uint32_t saddr, const void* gptr) {
    asm volatile("cp.async.cg.shared.global [%0], [%1], 16;\n" ::"r"(saddr), "l"(gptr));
}
#define CP_COMMIT() asm volatile("cp.async.commit_group;\n" ::: "memory")
#define CP_WAIT1()  asm volatile("cp.async.wait_group 1;\n" ::: "memory")

__device__ __forceinline__ float sigmoidf_(float x) { return 1.f / (1.f + __expf(-x)); }

// ---------------------------------------------------------------------------
// tf32 pre-conversion (rna) of weights / x.
// ---------------------------------------------------------------------------
__global__ void cvt_k(const float4* __restrict__ in, float4* __restrict__ out, int n4) {
    int i = blockIdx.x * blockDim.x + threadIdx.x;
    if (i >= n4) return;
    float4 v = in[i];
    v.x = to_tf32(v.x); v.y = to_tf32(v.y);
    v.z = to_tf32(v.z); v.w = to_tf32(v.w);
    out[i] = v;
}

// ---------------------------------------------------------------------------
// Mailbox pre-reduction routed by edge label (outputs tf32-rounded).
// ---------------------------------------------------------------------------
__global__ void prep_hsum(const float* __restrict__ hm, const float* __restrict__ el) {
    int idx = blockIdx.x * blockDim.x + threadIdx.x;
    if (idx >= Nn * Hh) return;
    int n = idx >> 9;
    int h = idx & 511;
    const float* hp = hm + (size_t)n * Kmb * Hh + h;
    const float* ep = el + n * Kmb;
    float s0 = 0.f, s1 = 0.f;
#pragma unroll
    for (int k = 0; k < Kmb; k++) {
        float e = ep[k];
        float v = hp[(size_t)k * Hh];
        float ev = e * v;
        s1 += ev;
        s0 += v - ev;
    }
    g_hsum2[(size_t)n * H2v + h]      = to_tf32(s0);
    g_hsum2[(size_t)n * H2v + Hh + h] = to_tf32(s1);
}

// ---------------------------------------------------------------------------
// Generic tf32 GEMM, C[M,Nc] (+)= A[M,Kd] @ B[Kd,Nc].
// A, B must be tf32-pre-rounded. 256 threads, block 256x128, warp 64x64.
// cp.async 3-stage pipeline, XOR-swizzled smem:
//   A [m][32]:  phys 16B-chunk = chunk ^ (m&7)
//   B [k][128]: phys 16B-chunk = chunk ^ ((k&3)<<1)
// ---------------------------------------------------------------------------
template <bool ACCUM>
__global__ void __launch_bounds__(256, 1) gemm_k(const float* __restrict__ A,
                                                 const float* __restrict__ B,
                                                 float* __restrict__ C,
                                                 int M, int Kd, int Nc) {
    extern __shared__ float smem[];
    const int tid = threadIdx.x, lane = tid & 31, wid = tid >> 5;
    const int g = lane >> 2, tg = lane & 3;
    const int wr = wid >> 1, wc = wid & 1;           // 4x2 warp grid
    const int m0 = blockIdx.x * BM, n0 = blockIdx.y * BN;
    const uint32_t sb = (uint32_t)__cvta_generic_to_shared(smem);

    float acc[4][8][4];
#pragma unroll
    for (int a = 0; a < 4; a++)
#pragma unroll
        for (int b = 0; b < 8; b++)
#pragma unroll
            for (int c = 0; c < 4; c++) acc[a][b][c] = 0.f;

    auto issue = [&](int kt, int st) {
        {   // A: thread tid copies its whole row (8 x 16B)
            const float* src = A + (size_t)(m0 + tid) * Kd + kt * BK;
            uint32_t dst = sb + (uint32_t)(st * STAGE_ELEM + tid * 32) * 4;
#pragma unroll
            for (int c = 0; c < 8; c++)
                cp16(dst + (uint32_t)((c ^ (tid & 7)) << 4), src + c * 4);
        }
        {   // B: 8 threads per k-row, 4 x 16B each
            const int k = tid >> 3, cb = tid & 7;
            const float* src = B + (size_t)(kt * BK + k) * Nc + n0;
            uint32_t dst = sb + (uint32_t)(st * STAGE_ELEM + A_ELEM + k * 128) * 4;
#pragma unroll
            for (int i = 0; i < 4; i++) {
                int c = cb + i * 8;
                cp16(dst + (uint32_t)((c ^ ((k & 3) << 1)) << 4), src + c * 4);
            }
        }
    };

    auto compute = [&](int st) {
        const float* sA = smem + st * STAGE_ELEM;
        const float* sB = sA + A_ELEM;
#pragma unroll
        for (int ks = 0; ks < 4; ks++) {
            const int cA = ks * 2;
            uint32_t af[4][4], bf[8][2];
#pragma unroll
            for (int mi = 0; mi < 4; mi++) {
                const float* p = sA + (wr * 64 + mi * 16 + g) * 32 + tg;
                const int o0 = (cA ^ g) << 2, o1 = ((cA + 1) ^ g) << 2;
                af[mi][0] = __float_as_uint(p[o0]);
                af[mi][2] = __float_as_uint(p[o1]);
                af[mi][1] = __float_as_uint(p[256 + o0]);
                af[mi][3] = __float_as_uint(p[256 + o1]);
            }
            const float* q = sB + (ks * 8 + tg) * 128 + (g & 3);
#pragma unroll
            for (int ni = 0; ni < 8; ni++) {
                const int cX = ((wc * 16 + ni * 2 + (g >> 2)) ^ (tg << 1)) << 2;
                bf[ni][0] = __float_as_uint(q[cX]);
                bf[ni][1] = __float_as_uint(q[512 + cX]);
            }
#pragma unroll
            for (int mi = 0; mi < 4; mi++)
#pragma unroll
                for (int ni = 0; ni < 8; ni++)
                    mma8(acc[mi][ni], af[mi][0], af[mi][1], af[mi][2], af[mi][3],
                         bf[ni][0], bf[ni][1]);
        }
    };

    const int KT = Kd / BK;
    issue(0, 0); CP_COMMIT();
    issue(1, 1); CP_COMMIT();
    for (int kt = 0; kt < KT; kt++) {
        CP_WAIT1();
        __syncthreads();
        if (kt + 2 < KT) issue(kt + 2, (kt + 2) % 3);
        CP_COMMIT();
        compute(kt % 3);
    }

#pragma unroll
    for (int mi = 0; mi < 4; mi++) {
#pragma unroll
        for (int ni = 0; ni < 8; ni++) {
            const int r0 = m0 + wr * 64 + mi * 16 + g;
            const int c0 = n0 + wc * 64 + ni * 8 + 2 * tg;
            float* p0 = C + (size_t)r0 * Nc + c0;
            float* p1 = C + (size_t)(r0 + 8) * Nc + c0;
            if (ACCUM) {
                float2 o0 = *(float2*)p0, o1 = *(float2*)p1;
                o0.x += acc[mi][ni][0]; o0.y += acc[mi][ni][1];
                o1.x += acc[mi][ni][2]; o1.y += acc[mi][ni][3];
                *(float2*)p0 = o0;
                *(float2*)p1 = o1;
            } else {
                *(float2*)p0 = make_float2(acc[mi][ni][0], acc[mi][ni][1]);
                *(float2*)p1 = make_float2(acc[mi][ni][2], acc[mi][ni][3]);
            }
        }
    }
}

// ---------------------------------------------------------------------------
// Fused F GEMM over (n,k) rows: contraction over 2H where A[row, 0:H]=(1-e)h,
// A[row, H:2H]=e*h. Raw h_mail tiles stream in via cp.async; the e-scaling and
// tf32 rna rounding are applied at fragment-load time (fma/alu pipes are idle).
// Epilogue: f = sigmoid(acc + wf_x + b_f); c_agg = sum_k f * c_mail (warp-local).
// ---------------------------------------------------------------------------
__global__ void __launch_bounds__(256, 1) fgemm(const float* __restrict__ hm,
                                                const float* __restrict__ el,
                                                const float* __restrict__ cm,
                                                const float* __restrict__ Uf,
                                                const float* __restrict__ bfv) {
    extern __shared__ float smem[];
    const int tid = threadIdx.x, lane = tid & 31, wid = tid >> 5;
    const int g = lane >> 2, tg = lane & 3;
    const int wr = wid >> 1, wc = wid & 1;
    const int m0 = blockIdx.x * BM;      // over NK rows
    const int n0 = blockIdx.y * BN;      // over H cols
    const int Nc = Hh, Kd = H2v;
    const uint32_t sb = (uint32_t)__cvta_generic_to_shared(smem);

    float acc[4][8][4];
#pragma unroll
    for (int a = 0; a < 4; a++)
#pragma unroll
        for (int b = 0; b < 8; b++)
#pragma unroll
            for (int c = 0; c < 4; c++) acc[a][b][c] = 0.f;

    // edge labels for the rows this thread's fragments own
    float e0[4], e1[4];
#pragma unroll
    for (int mi = 0; mi < 4; mi++) {
        const int r = m0 + wr * 64 + mi * 16 + g;
        e0[mi] = __ldg(el + r);
        e1[mi] = __ldg(el + r + 8);
    }
    float s0[4], s1[4];

    auto issue = [&](int kt, int st) {
        {   // A: raw h_mail row slice (col folded mod H)
            const float* src = hm + (size_t)(m0 + tid) * Hh + ((kt * BK) & (Hh - 1));
            uint32_t dst = sb + (uint32_t)(st * STAGE_ELEM + tid * 32) * 4;
#pragma unroll
            for (int c = 0; c < 8; c++)
                cp16(dst + (uint32_t)((c ^ (tid & 7)) << 4), src + c * 4);
        }
        {   // B = U_f (tf32 pre-rounded)
            const int k = tid >> 3, cb = tid & 7;
            const float* src = Uf + (size_t)(kt * BK + k) * Nc + n0;
            uint32_t dst = sb + (uint32_t)(st * STAGE_ELEM + A_ELEM + k * 128) * 4;
#pragma unroll
            for (int i = 0; i < 4; i++) {
                int c = cb + i * 8;
                cp16(dst + (uint32_t)((c ^ ((k & 3) << 1)) << 4), src + c * 4);
            }
        }
    };

    auto compute = [&](int st) {
        const float* sA = smem + st * STAGE_ELEM;
        const float* sB = sA + A_ELEM;
#pragma unroll
        for (int ks = 0; ks < 4; ks++) {
            const int cA = ks * 2;
            uint32_t af[4][4], bf[8][2];
#pragma unroll
            for (int mi = 0; mi < 4; mi++) {
                const float* p = sA + (wr * 64 + mi * 16 + g) * 32 + tg;
                const int o0 = (cA ^ g) << 2, o1 = ((cA + 1) ^ g) << 2;
                af[mi][0] = tf32b(s0[mi] * p[o0]);
                af[mi][2] = tf32b(s0[mi] * p[o1]);
                af[mi][1] = tf32b(s1[mi] * p[256 + o0]);
                af[mi][3] = tf32b(s1[mi] * p[256 + o1]);
            }
            const float* q = sB + (ks * 8 + tg) * 128 + (g & 3);
#pragma unroll
            for (int ni = 0; ni < 8; ni++) {
                const int cX = ((wc * 16 + ni * 2 + (g >> 2)) ^ (tg << 1)) << 2;
                bf[ni][0] = __float_as_uint(q[cX]);
                bf[ni][1] = __float_as_uint(q[512 + cX]);
            }
#pragma unroll
            for (int mi = 0; mi < 4; mi++)
#pragma unroll
                for (int ni = 0; ni < 8; ni++)
                    mma8(acc[mi][ni], af[mi][0], af[mi][1], af[mi][2], af[mi][3],
                         bf[ni][0], bf[ni][1]);
        }
    };

    const int KT = Kd / BK;   // 32
    issue(0, 0); CP_COMMIT();
    issue(1, 1); CP_COMMIT();
    for (int kt = 0; kt < KT; kt++) {
        const bool hi = (kt * BK >= Hh);
#pragma unroll
        for (int mi = 0; mi < 4; mi++) {
            s0[mi] = hi ? e0[mi] : 1.f - e0[mi];
            s1[mi] = hi ? e1[mi] : 1.f - e1[mi];
        }
        CP_WAIT1();
        __syncthreads();
        if (kt + 2 < KT) issue(kt + 2, (kt + 2) % 3);
        CP_COMMIT();
        compute(kt % 3);
    }

    // Fused epilogue: f = sigmoid(acc + wf_x + b_f); reduce f*c_mail over k.
#pragma unroll
    for (int mi = 0; mi < 4; mi++) {
        const int rbase = m0 + wr * 64 + mi * 16;   // 16 rows = nodes nA, nA+1
        const int nA = rbase >> 3;
#pragma unroll
        for (int ni = 0; ni < 8; ni++) {
            const int gc = n0 + wc * 64 + ni * 8 + 2 * tg;
            const float b0 = bfv[gc], b1 = bfv[gc + 1];
            const float wA0 = g_wfx[(size_t)nA * Hh + gc];
            const float wA1 = g_wfx[(size_t)nA * Hh + gc + 1];
            const float wB0 = g_wfx[(size_t)(nA + 1) * Hh + gc];
            const float wB1 = g_wfx[(size_t)(nA + 1) * Hh + gc + 1];
            const int rA = rbase + g;
            const float2 cA = *(const float2*)(cm + (size_t)rA * Hh + gc);
            const float2 cB = *(const float2*)(cm + (size_t)(rA + 8) * Hh + gc);
            float v0 = sigmoidf_(acc[mi][ni][0] + wA0 + b0) * cA.x;
            float v1 = sigmoidf_(acc[mi][ni][1] + wA1 + b1) * cA.y;
            float v2 = sigmoidf_(acc[mi][ni][2] + wB0 + b0) * cB.x;
            float v3 = sigmoidf_(acc[mi][ni][3] + wB1 + b1) * cB.y;
            // sum over the 8 rows of each node = lanes differing in bits 2..4
#pragma unroll
            for (int m = 4; m <= 16; m <<= 1) {
                v0 += __shfl_xor_sync(0xFFFFFFFFu, v0, m);
                v1 += __shfl_xor_sync(0xFFFFFFFFu, v1, m);
                v2 += __shfl_xor_sync(0xFFFFFFFFu, v2, m);
                v3 += __shfl_xor_sync(0xFFFFFFFFu, v3, m);
            }
            if (lane < 4) {
                *(float2*)(g_cagg + (size_t)nA * Hh + gc)       = make_float2(v0, v1);
                *(float2*)(g_cagg + (size_t)(nA + 1) * Hh + gc) = make_float2(v2, v3);
            }
        }
    }
}

// ---------------------------------------------------------------------------
// Final elementwise epilogue: gates + cell/hidden state.  out = [h ; c]
// ---------------------------------------------------------------------------
__global__ void final_ep(const float* __restrict__ biou, float* __restrict__ out) {
    int idx = blockIdx.x * blockDim.x + threadIdx.x;
    if (idx >= Nn * Hh) return;
    int n = idx >> 9;
    int h = idx & 511;
    const float* row = g_iou + (size_t)n * H3v;
    float iv = sigmoidf_(row[h] + biou[h]);
    float ov = sigmoidf_(row[Hh + h] + biou[Hh + h]);
    float uv = tanhf(row[2 * Hh + h] + biou[2 * Hh + h]);
    float c = iv * uv + g_cagg[idx];
    out[idx]           = ov * tanhf(c);   // h
    out[Nn * Hh + idx] = c;               // c
}

// ---------------------------------------------------------------------------
extern "C" void kernel_launch(void* const* d_in, const int* in_sizes, int n_in,
                              void* d_out, int out_size) {
    const float* x    = (const float*)d_in[0];
    const float* hm   = (const float*)d_in[1];
    const float* cm   = (const float*)d_in[2];
    const float* el   = (const float*)d_in[3];
    const float* Wiou = (const float*)d_in[4];
    const float* Wf   = (const float*)d_in[5];
    const float* Uiou = (const float*)d_in[6];
    const float* Uf   = (const float*)d_in[7];
    const float* biou = (const float*)d_in[8];
    const float* bfv  = (const float*)d_in[9];
    float* out = (float*)d_out;

    float *p_wfx, *p_iou, *p_hsum2, *p_xt, *p_wiou, *p_wf, *p_uiou, *p_uf;
    cudaGetSymbolAddress((void**)&p_wfx, g_wfx);
    cudaGetSymbolAddress((void**)&p_iou, g_iou);
    cudaGetSymbolAddress((void**)&p_hsum2, g_hsum2);
    cudaGetSymbolAddress((void**)&p_xt, g_xt);
    cudaGetSymbolAddress((void**)&p_wiou, g_wiou_t);
    cudaGetSymbolAddress((void**)&p_wf, g_wf_t);
    cudaGetSymbolAddress((void**)&p_uiou, g_uiou_t);
    cudaGetSymbolAddress((void**)&p_uf, g_uf_t);

    cudaFuncSetAttribute(gemm_k<false>, cudaFuncAttributeMaxDynamicSharedMemorySize, SMEM_BYTES);
    cudaFuncSetAttribute(gemm_k<true>,  cudaFuncAttributeMaxDynamicSharedMemorySize, SMEM_BYTES);
    cudaFuncSetAttribute(fgemm,         cudaFuncAttributeMaxDynamicSharedMemorySize, SMEM_BYTES);

    auto cvt = [&](const float* in, float* o, int n) {
        int n4 = n / 4;
        cvt_k<<<(n4 + 255) / 256, 256>>>((const float4*)in, (float4*)o, n4);
    };

    // tf32 pre-rounding of GEMM operands
    cvt(x, p_xt, Nn * Xx);
    cvt(Wiou, p_wiou, Xx * H3v);
    cvt(Wf, p_wf, Xx * Hh);
    cvt(Uiou, p_uiou, H2v * H3v);
    cvt(Uf, p_uf, H2v * Hh);

    // mailbox pre-reduction (tf32 output)
    prep_hsum<<<(Nn * Hh + 255) / 256, 256>>>(hm, el);

    // wf_x = x @ W_f
    gemm_k<false><<<dim3(Nn / BM, Hh / BN), 256, SMEM_BYTES>>>(p_xt, p_wf, p_wfx, Nn, Xx, Hh);
    // iou = x @ W_iou ; iou += hsum2 @ U_iou
    gemm_k<false><<<dim3(Nn / BM, H3v / BN), 256, SMEM_BYTES>>>(p_xt, p_wiou, p_iou, Nn, Xx, H3v);
    gemm_k<true><<<dim3(Nn / BM, H3v / BN), 256, SMEM_BYTES>>>(p_hsum2, p_uiou, p_iou, Nn, H2v, H3v);
    // fused f-gate GEMM + c_agg reduction (needs wf_x)
    fgemm<<<dim3(NK / BM, Hh / BN), 256, SMEM_BYTES>>>(hm, el, cm, p_uf, bfv);
    // gates + outputs
    final_ep<<<(Nn * Hh + 255) / 256, 256>>>(biou, out);
}

// round 4
// speedup vs baseline: 1.3619x; 1.3619x over previous
#include <cuda_runtime.h>
#include <cstdint>
#include <math.h>

// ---------------------------------------------------------------------------
// ImprovedGraphLSTMCell  (N=8192, K=8, H=512, X=512)
// tf32 mma.sync m16n8k8, fp32 accumulate, rna-rounded operands.
// R4: R3 design with the A-tile cp.async loader fixed to be coalesced
//     (8 threads cooperate per 128B row instead of 1 thread per row).
// ---------------------------------------------------------------------------

namespace {
constexpr int Nn  = 8192;
constexpr int Kmb = 8;
constexpr int Hh  = 512;
constexpr int Xx  = 512;
constexpr int NK  = Nn * Kmb;     // 65536
constexpr int H2v = 2 * Hh;       // 1024
constexpr int H3v = 3 * Hh;       // 1536

constexpr int BM = 256, BN = 128, BK = 32;
constexpr int A_ELEM = BM * BK;           // 8192 floats
constexpr int B_ELEM = BK * BN;           // 4096 floats
constexpr int STAGE_ELEM = A_ELEM + B_ELEM;
constexpr int SMEM_BYTES = 3 * STAGE_ELEM * 4;  // 147456
}

// Scratch (device globals — no allocation allowed)
__device__ float g_wfx[Nn * Hh];
__device__ float g_iou[Nn * H3v];
__device__ float g_hsum2[Nn * H2v];
__device__ float g_cagg[Nn * Hh];
__device__ float g_xt[Nn * Xx];
__device__ float g_wiou_t[Xx * H3v];
__device__ float g_wf_t[Xx * Hh];
__device__ float g_uiou_t[H2v * H3v];
__device__ float g_uf_t[H2v * Hh];

__device__ __forceinline__ uint32_t tf32b(float x) {
    uint32_t r;
    asm("cvt.rna.tf32.f32 %0, %1;" : "=r"(r) : "f"(x));
    return r;
}
__device__ __forceinline__ float to_tf32(float x) { return __uint_as_float(tf32b(x)); }

__device__ __forceinline__ void mma8(float c[4],
                                     uint32_t a0, uint32_t a1, uint32_t a2, uint32_t a3,
                                     uint32_t b0, uint32_t b1) {
    asm volatile(
        "mma.sync.aligned.m16n8k8.row.col.f32.tf32.tf32.f32 "
        "{%0,%1,%2,%3}, {%4,%5,%6,%7}, {%8,%9}, {%0,%1,%2,%3};\n"
        : "+f"(c[0]), "+f"(c[1]), "+f"(c[2]), "+f"(c[3])
        : "r"(a0), "r"(a1), "r"(a2), "r"(a3), "r"(b0), "r"(b1));
}

__device__ __forceinline__ void cp16(uint32_t saddr, const void* gptr) {
    asm volatile("cp.async.cg.shared.global [%0], [%1], 16;\n" ::"r"(saddr), "l"(gptr));
}
#define CP_COMMIT() asm volatile("cp.async.commit_group;\n" ::: "memory")
#define CP_WAIT1()  asm volatile("cp.async.wait_group 1;\n" ::: "memory")

__device__ __forceinline__ float sigmoidf_(float x) { return 1.f / (1.f + __expf(-x)); }

// ---------------------------------------------------------------------------
// tf32 pre-conversion (rna) of weights / x.
// ---------------------------------------------------------------------------
__global__ void cvt_k(const float4* __restrict__ in, float4* __restrict__ out, int n4) {
    int i = blockIdx.x * blockDim.x + threadIdx.x;
    if (i >= n4) return;
    float4 v = in[i];
    v.x = to_tf32(v.x); v.y = to_tf32(v.y);
    v.z = to_tf32(v.z); v.w = to_tf32(v.w);
    out[i] = v;
}

// ---------------------------------------------------------------------------
// Mailbox pre-reduction routed by edge label (outputs tf32-rounded).
// ---------------------------------------------------------------------------
__global__ void prep_hsum(const float* __restrict__ hm, const float* __restrict__ el) {
    int idx = blockIdx.x * blockDim.x + threadIdx.x;
    if (idx >= Nn * Hh) return;
    int n = idx >> 9;
    int h = idx & 511;
    const float* hp = hm + (size_t)n * Kmb * Hh + h;
    const float* ep = el + n * Kmb;
    float s0 = 0.f, s1 = 0.f;
#pragma unroll
    for (int k = 0; k < Kmb; k++) {
        float e = ep[k];
        float v = hp[(size_t)k * Hh];
        float ev = e * v;
        s1 += ev;
        s0 += v - ev;
    }
    g_hsum2[(size_t)n * H2v + h]      = to_tf32(s0);
    g_hsum2[(size_t)n * H2v + Hh + h] = to_tf32(s1);
}

// ---------------------------------------------------------------------------
// Generic tf32 GEMM, C[M,Nc] (+)= A[M,Kd] @ B[Kd,Nc].
// A, B must be tf32-pre-rounded. 256 threads, block 256x128, warp 64x64.
// cp.async 3-stage pipeline, XOR-swizzled smem (conflict-free, verified):
//   A [m][32]:  phys 16B-chunk = chunk ^ (m&7)
//   B [k][128]: phys 16B-chunk = chunk ^ ((k&3)<<1)
// A loader: 8 threads per row (chunk = tid&7, rows (tid>>3)+32i) — 4 full
// 128B lines per warp-instruction, fully coalesced.
// ---------------------------------------------------------------------------
template <bool ACCUM>
__global__ void __launch_bounds__(256, 1) gemm_k(const float* __restrict__ A,
                                                 const float* __restrict__ B,
                                                 float* __restrict__ C,
                                                 int M, int Kd, int Nc) {
    extern __shared__ float smem[];
    const int tid = threadIdx.x, lane = tid & 31, wid = tid >> 5;
    const int g = lane >> 2, tg = lane & 3;
    const int wr = wid >> 1, wc = wid & 1;           // 4x2 warp grid
    const int m0 = blockIdx.x * BM, n0 = blockIdx.y * BN;
    const uint32_t sb = (uint32_t)__cvta_generic_to_shared(smem);

    float acc[4][8][4];
#pragma unroll
    for (int a = 0; a < 4; a++)
#pragma unroll
        for (int b = 0; b < 8; b++)
#pragma unroll
            for (int c = 0; c < 4; c++) acc[a][b][c] = 0.f;

    // A loader indices: chunk cbA of rows rA0+32i
    const int cbA = tid & 7, rA0 = tid >> 3;
    const uint32_t swA = (uint32_t)((cbA ^ (rA0 & 7)) << 4);   // constant per thread
    // B loader indices
    const int kB = tid >> 3, cbB = tid & 7;

    auto issue = [&](int kt, int st) {
        {   // A: coalesced — 8 threads cover one 128B row
            const float* src = A + (size_t)(m0 + rA0) * Kd + kt * BK + cbA * 4;
            uint32_t dst = sb + (uint32_t)(st * STAGE_ELEM + rA0 * 32) * 4 + swA;
#pragma unroll
            for (int i = 0; i < 8; i++)
                cp16(dst + (uint32_t)(i * 32 * 32) * 4, src + (size_t)(i * 32) * Kd);
        }
        {   // B: 8 threads per k-row, 4 x 16B each (coalesced)
            const float* src = B + (size_t)(kt * BK + kB) * Nc + n0;
            uint32_t dst = sb + (uint32_t)(st * STAGE_ELEM + A_ELEM + kB * 128) * 4;
#pragma unroll
            for (int i = 0; i < 4; i++) {
                int c = cbB + i * 8;
                cp16(dst + (uint32_t)((c ^ ((kB & 3) << 1)) << 4), src + c * 4);
            }
        }
    };

    auto compute = [&](int st) {
        const float* sA = smem + st * STAGE_ELEM;
        const float* sB = sA + A_ELEM;
#pragma unroll
        for (int ks = 0; ks < 4; ks++) {
            const int cA = ks * 2;
            uint32_t af[4][4], bf[8][2];
#pragma unroll
            for (int mi = 0; mi < 4; mi++) {
                const float* p = sA + (wr * 64 + mi * 16 + g) * 32 + tg;
                const int o0 = (cA ^ g) << 2, o1 = ((cA + 1) ^ g) << 2;
                af[mi][0] = __float_as_uint(p[o0]);
                af[mi][2] = __float_as_uint(p[o1]);
                af[mi][1] = __float_as_uint(p[256 + o0]);
                af[mi][3] = __float_as_uint(p[256 + o1]);
            }
            const float* q = sB + (ks * 8 + tg) * 128 + (g & 3);
#pragma unroll
            for (int ni = 0; ni < 8; ni++) {
                const int cX = ((wc * 16 + ni * 2 + (g >> 2)) ^ (tg << 1)) << 2;
                bf[ni][0] = __float_as_uint(q[cX]);
                bf[ni][1] = __float_as_uint(q[512 + cX]);
            }
#pragma unroll
            for (int mi = 0; mi < 4; mi++)
#pragma unroll
                for (int ni = 0; ni < 8; ni++)
                    mma8(acc[mi][ni], af[mi][0], af[mi][1], af[mi][2], af[mi][3],
                         bf[ni][0], bf[ni][1]);
        }
    };

    const int KT = Kd / BK;
    issue(0, 0); CP_COMMIT();
    issue(1, 1); CP_COMMIT();
    for (int kt = 0; kt < KT; kt++) {
        CP_WAIT1();
        __syncthreads();
        if (kt + 2 < KT) issue(kt + 2, (kt + 2) % 3);
        CP_COMMIT();
        compute(kt % 3);
    }

#pragma unroll
    for (int mi = 0; mi < 4; mi++) {
#pragma unroll
        for (int ni = 0; ni < 8; ni++) {
            const int r0 = m0 + wr * 64 + mi * 16 + g;
            const int c0 = n0 + wc * 64 + ni * 8 + 2 * tg;
            float* p0 = C + (size_t)r0 * Nc + c0;
            float* p1 = C + (size_t)(r0 + 8) * Nc + c0;
            if (ACCUM) {
                float2 o0 = *(float2*)p0, o1 = *(float2*)p1;
                o0.x += acc[mi][ni][0]; o0.y += acc[mi][ni][1];
                o1.x += acc[mi][ni][2]; o1.y += acc[mi][ni][3];
                *(float2*)p0 = o0;
                *(float2*)p1 = o1;
            } else {
                *(float2*)p0 = make_float2(acc[mi][ni][0], acc[mi][ni][1]);
                *(float2*)p1 = make_float2(acc[mi][ni][2], acc[mi][ni][3]);
            }
        }
    }
}

// ---------------------------------------------------------------------------
// Fused F GEMM over (n,k) rows: contraction over 2H where A[row,0:H]=(1-e)h,
// A[row,H:2H]=e*h. Raw h_mail streams via cp.async (coalesced); e-scaling and
// tf32 rounding at fragment-load time. Epilogue: f = sigmoid(acc+wf_x+b_f);
// c_agg = sum_k f * c_mail (warp-local shuffle reduction).
// ---------------------------------------------------------------------------
__global__ void __launch_bounds__(256, 1) fgemm(const float* __restrict__ hm,
                                                const float* __restrict__ el,
                                                const float* __restrict__ cm,
                                                const float* __restrict__ Uf,
                                                const float* __restrict__ bfv) {
    extern __shared__ float smem[];
    const int tid = threadIdx.x, lane = tid & 31, wid = tid >> 5;
    const int g = lane >> 2, tg = lane & 3;
    const int wr = wid >> 1, wc = wid & 1;
    const int m0 = blockIdx.x * BM;      // over NK rows
    const int n0 = blockIdx.y * BN;      // over H cols
    const int Nc = Hh;
    const uint32_t sb = (uint32_t)__cvta_generic_to_shared(smem);

    float acc[4][8][4];
#pragma unroll
    for (int a = 0; a < 4; a++)
#pragma unroll
        for (int b = 0; b < 8; b++)
#pragma unroll
            for (int c = 0; c < 4; c++) acc[a][b][c] = 0.f;

    float e0[4], e1[4];
#pragma unroll
    for (int mi = 0; mi < 4; mi++) {
        const int r = m0 + wr * 64 + mi * 16 + g;
        e0[mi] = __ldg(el + r);
        e1[mi] = __ldg(el + r + 8);
    }
    float s0[4], s1[4];

    const int cbA = tid & 7, rA0 = tid >> 3;
    const uint32_t swA = (uint32_t)((cbA ^ (rA0 & 7)) << 4);
    const int kB = tid >> 3, cbB = tid & 7;

    auto issue = [&](int kt, int st) {
        {   // A: raw h_mail rows (col folded mod H), coalesced
            const float* src = hm + (size_t)(m0 + rA0) * Hh + ((kt * BK) & (Hh - 1)) + cbA * 4;
            uint32_t dst = sb + (uint32_t)(st * STAGE_ELEM + rA0 * 32) * 4 + swA;
#pragma unroll
            for (int i = 0; i < 8; i++)
                cp16(dst + (uint32_t)(i * 32 * 32) * 4, src + (size_t)(i * 32) * Hh);
        }
        {   // B = U_f (tf32 pre-rounded)
            const float* src = Uf + (size_t)(kt * BK + kB) * Nc + n0;
            uint32_t dst = sb + (uint32_t)(st * STAGE_ELEM + A_ELEM + kB * 128) * 4;
#pragma unroll
            for (int i = 0; i < 4; i++) {
                int c = cbB + i * 8;
                cp16(dst + (uint32_t)((c ^ ((kB & 3) << 1)) << 4), src + c * 4);
            }
        }
    };

    auto compute = [&](int st) {
        const float* sA = smem + st * STAGE_ELEM;
        const float* sB = sA + A_ELEM;
#pragma unroll
        for (int ks = 0; ks < 4; ks++) {
            const int cA = ks * 2;
            uint32_t af[4][4], bf[8][2];
#pragma unroll
            for (int mi = 0; mi < 4; mi++) {
                const float* p = sA + (wr * 64 + mi * 16 + g) * 32 + tg;
                const int o0 = (cA ^ g) << 2, o1 = ((cA + 1) ^ g) << 2;
                af[mi][0] = tf32b(s0[mi] * p[o0]);
                af[mi][2] = tf32b(s0[mi] * p[o1]);
                af[mi][1] = tf32b(s1[mi] * p[256 + o0]);
                af[mi][3] = tf32b(s1[mi] * p[256 + o1]);
            }
            const float* q = sB + (ks * 8 + tg) * 128 + (g & 3);
#pragma unroll
            for (int ni = 0; ni < 8; ni++) {
                const int cX = ((wc * 16 + ni * 2 + (g >> 2)) ^ (tg << 1)) << 2;
                bf[ni][0] = __float_as_uint(q[cX]);
                bf[ni][1] = __float_as_uint(q[512 + cX]);
            }
#pragma unroll
            for (int mi = 0; mi < 4; mi++)
#pragma unroll
                for (int ni = 0; ni < 8; ni++)
                    mma8(acc[mi][ni], af[mi][0], af[mi][1], af[mi][2], af[mi][3],
                         bf[ni][0], bf[ni][1]);
        }
    };

    const int KT = H2v / BK;   // 32
    issue(0, 0); CP_COMMIT();
    issue(1, 1); CP_COMMIT();
    for (int kt = 0; kt < KT; kt++) {
        const bool hi = (kt * BK >= Hh);
#pragma unroll
        for (int mi = 0; mi < 4; mi++) {
            s0[mi] = hi ? e0[mi] : 1.f - e0[mi];
            s1[mi] = hi ? e1[mi] : 1.f - e1[mi];
        }
        CP_WAIT1();
        __syncthreads();
        if (kt + 2 < KT) issue(kt + 2, (kt + 2) % 3);
        CP_COMMIT();
        compute(kt % 3);
    }

    // Fused epilogue
#pragma unroll
    for (int mi = 0; mi < 4; mi++) {
        const int rbase = m0 + wr * 64 + mi * 16;   // 16 rows = nodes nA, nA+1
        const int nA = rbase >> 3;
#pragma unroll
        for (int ni = 0; ni < 8; ni++) {
            const int gc = n0 + wc * 64 + ni * 8 + 2 * tg;
            const float b0 = bfv[gc], b1 = bfv[gc + 1];
            const float wA0 = g_wfx[(size_t)nA * Hh + gc];
            const float wA1 = g_wfx[(size_t)nA * Hh + gc + 1];
            const float wB0 = g_wfx[(size_t)(nA + 1) * Hh + gc];
            const float wB1 = g_wfx[(size_t)(nA + 1) * Hh + gc + 1];
            const int rA = rbase + g;
            const float2 cA = *(const float2*)(cm + (size_t)rA * Hh + gc);
            const float2 cB = *(const float2*)(cm + (size_t)(rA + 8) * Hh + gc);
            float v0 = sigmoidf_(acc[mi][ni][0] + wA0 + b0) * cA.x;
            float v1 = sigmoidf_(acc[mi][ni][1] + wA1 + b1) * cA.y;
            float v2 = sigmoidf_(acc[mi][ni][2] + wB0 + b0) * cB.x;
            float v3 = sigmoidf_(acc[mi][ni][3] + wB1 + b1) * cB.y;
#pragma unroll
            for (int m = 4; m <= 16; m <<= 1) {
                v0 += __shfl_xor_sync(0xFFFFFFFFu, v0, m);
                v1 += __shfl_xor_sync(0xFFFFFFFFu, v1, m);
                v2 += __shfl_xor_sync(0xFFFFFFFFu, v2, m);
                v3 += __shfl_xor_sync(0xFFFFFFFFu, v3, m);
            }
            if (lane < 4) {
                *(float2*)(g_cagg + (size_t)nA * Hh + gc)       = make_float2(v0, v1);
                *(float2*)(g_cagg + (size_t)(nA + 1) * Hh + gc) = make_float2(v2, v3);
            }
        }
    }
}

// ---------------------------------------------------------------------------
// Final elementwise epilogue: gates + cell/hidden state.  out = [h ; c]
// ---------------------------------------------------------------------------
__global__ void final_ep(const float* __restrict__ biou, float* __restrict__ out) {
    int idx = blockIdx.x * blockDim.x + threadIdx.x;
    if (idx >= Nn * Hh) return;
    int n = idx >> 9;
    int h = idx & 511;
    const float* row = g_iou + (size_t)n * H3v;
    float iv = sigmoidf_(row[h] + biou[h]);
    float ov = sigmoidf_(row[Hh + h] + biou[Hh + h]);
    float uv = tanhf(row[2 * Hh + h] + biou[2 * Hh + h]);
    float c = iv * uv + g_cagg[idx];
    out[idx]           = ov * tanhf(c);   // h
    out[Nn * Hh + idx] = c;               // c
}

// ---------------------------------------------------------------------------
extern "C" void kernel_launch(void* const* d_in, const int* in_sizes, int n_in,
                              void* d_out, int out_size) {
    const float* x    = (const float*)d_in[0];
    const float* hm   = (const float*)d_in[1];
    const float* cm   = (const float*)d_in[2];
    const float* el   = (const float*)d_in[3];
    const float* Wiou = (const float*)d_in[4];
    const float* Wf   = (const float*)d_in[5];
    const float* Uiou = (const float*)d_in[6];
    const float* Uf   = (const float*)d_in[7];
    const float* biou = (const float*)d_in[8];
    const float* bfv  = (const float*)d_in[9];
    float* out = (float*)d_out;

    float *p_wfx, *p_iou, *p_hsum2, *p_xt, *p_wiou, *p_wf, *p_uiou, *p_uf;
    cudaGetSymbolAddress((void**)&p_wfx, g_wfx);
    cudaGetSymbolAddress((void**)&p_iou, g_iou);
    cudaGetSymbolAddress((void**)&p_hsum2, g_hsum2);
    cudaGetSymbolAddress((void**)&p_xt, g_xt);
    cudaGetSymbolAddress((void**)&p_wiou, g_wiou_t);
    cudaGetSymbolAddress((void**)&p_wf, g_wf_t);
    cudaGetSymbolAddress((void**)&p_uiou, g_uiou_t);
    cudaGetSymbolAddress((void**)&p_uf, g_uf_t);

    cudaFuncSetAttribute(gemm_k<false>, cudaFuncAttributeMaxDynamicSharedMemorySize, SMEM_BYTES);
    cudaFuncSetAttribute(gemm_k<true>,  cudaFuncAttributeMaxDynamicSharedMemorySize, SMEM_BYTES);
    cudaFuncSetAttribute(fgemm,         cudaFuncAttributeMaxDynamicSharedMemorySize, SMEM_BYTES);

    auto cvt = [&](const float* in, float* o, int n) {
        int n4 = n / 4;
        cvt_k<<<(n4 + 255) / 256, 256>>>((const float4*)in, (float4*)o, n4);
    };

    // tf32 pre-rounding of GEMM operands
    cvt(x, p_xt, Nn * Xx);
    cvt(Wiou, p_wiou, Xx * H3v);
    cvt(Wf, p_wf, Xx * Hh);
    cvt(Uiou, p_uiou, H2v * H3v);
    cvt(Uf, p_uf, H2v * Hh);

    // mailbox pre-reduction (tf32 output)
    prep_hsum<<<(Nn * Hh + 255) / 256, 256>>>(hm, el);

    // wf_x = x @ W_f
    gemm_k<false><<<dim3(Nn / BM, Hh / BN), 256, SMEM_BYTES>>>(p_xt, p_wf, p_wfx, Nn, Xx, Hh);
    // iou = x @ W_iou ; iou += hsum2 @ U_iou
    gemm_k<false><<<dim3(Nn / BM, H3v / BN), 256, SMEM_BYTES>>>(p_xt, p_wiou, p_iou, Nn, Xx, H3v);
    gemm_k<true><<<dim3(Nn / BM, H3v / BN), 256, SMEM_BYTES>>>(p_hsum2, p_uiou, p_iou, Nn, H2v, H3v);
    // fused f-gate GEMM + c_agg reduction (needs wf_x)
    fgemm<<<dim3(NK / BM, Hh / BN), 256, SMEM_BYTES>>>(hm, el, cm, p_uf, bfv);
    // gates + outputs
    final_ep<<<(Nn * Hh + 255) / 256, 256>>>(biou, out);
}